// round 11
// baseline (speedup 1.0000x reference)
#include <cuda_runtime.h>
#include <cuda_fp16.h>
#include <cstdint>

// LogicalConsistencyLoss: out = sum_{s,a,b,c} relu(M_ab - M_ac*M_bc) / (R*B)
// where M = fp16(sigmoid(logits)) * mask_a * mask_b per (batch,relation) slice.
// R11: R10 config, but the cb loop is a REAL loop (#pragma unroll 1):
//      mainloop body 35KB straight-line -> 8.8KB looped 4x (I$-resident).

#define B_ 2
#define N_ 512
#define R_ 4
#define S_ (B_ * R_)                   // 8 slices
#define NT (N_ / 128)                  // 4 tiles per dim
#define CS 16                          // c-split: 32 c's per CTA
#define NCTA (NT * NT * CS * S_)       // 2048 cubic CTAs / partials

__device__ __half    g_relh[S_ * N_ * N_];   // 4 MB scratch (L2-resident)
__device__ float     g_part[NCTA];
__device__ unsigned  g_ctr;                  // zero-init; reset by last CTA

// ---------------- Pass 1: sigmoid + mask -> fp16, de-interleave R ----------------
__global__ void sigmoid_mask_kernel(const float* __restrict__ logits,
                                    const int*   __restrict__ masks) {
    int idx = blockIdx.x * blockDim.x + threadIdx.x;  // over B*N*N
    if (idx >= B_ * N_ * N_) return;
    int b   = idx / (N_ * N_);
    int rem = idx - b * (N_ * N_);
    int i   = rem / N_;
    int j   = rem - i * N_;
    float mm = (masks[b * N_ + i] > 0 && masks[b * N_ + j] > 0) ? 1.0f : 0.0f;
    float4 v = ((const float4*)logits)[idx];  // 4 relations of one (b,i,j)
    float p0 = __fdividef(mm, 1.0f + __expf(-v.x));
    float p1 = __fdividef(mm, 1.0f + __expf(-v.y));
    float p2 = __fdividef(mm, 1.0f + __expf(-v.z));
    float p3 = __fdividef(mm, 1.0f + __expf(-v.w));
    g_relh[(b * R_ + 0) * N_ * N_ + rem] = __float2half(p0);
    g_relh[(b * R_ + 1) * N_ * N_ + rem] = __float2half(p1);
    g_relh[(b * R_ + 2) * N_ * N_ + rem] = __float2half(p2);
    g_relh[(b * R_ + 3) * N_ * N_ + rem] = __float2half(p3);
}

// ---------------- Pass 2: cubic relu contraction + fused final reduce ----------
// Grid: x = (a,b) tile (16), y = c-split (16), z = slice (8). 256 threads.
// Thread: 8x8 fp16 M_ab tile as 8x4 half2 regs; 8 half2 accs -> 2 f32.
__global__ void __launch_bounds__(256, 4)
trans_relu_kernel(float* __restrict__ out) {
    const int tile = blockIdx.x;      // 0..15
    const int cblk = blockIdx.y;      // 0..15
    const int sl   = blockIdx.z;      // 0..7
    const __half* __restrict__ M = g_relh + sl * N_ * N_;

    const int a0 = (tile / NT) * 128;
    const int b0 = (tile % NT) * 128;
    const int c0 = cblk * (N_ / CS);  // 32 c's per CTA

    const int tid = threadIdx.x;
    const int tx  = tid & 15;         // b sub-tile
    const int ty  = tid >> 4;         // a sub-tile

    // All 32 c's staged once.
    // sA holds NEGATED + DUPLICATED values: sA[c][2a]=sA[c][2a+1] = -M[a0+a][c]
    // so uint4 LDS yields 4 ready {-a,-a} half2 broadcast pairs.
    __shared__ __align__(16) __half sA[32][256];   // 16 KB
    __shared__ __align__(16) __half sB[32][128];   //  8 KB
    // Reduction scratch aliased into sA after the mainloop (post-sync).
    float*  wred  = reinterpret_cast<float*>(&sA[0][0]);   // 8 floats
    double* dw    = reinterpret_cast<double*>(&sA[1][0]);  // 8 doubles
    int*    lastf = reinterpret_cast<int*>(&sA[2][0]);     // amLast flag

    // 8x8 M_ab tile packed as half2 (j,j+1) pairs: 32 regs.
    __half2 mab2[8][4];
#pragma unroll
    for (int i = 0; i < 8; ++i) {
        uint4 q = *(const uint4*)(M + (a0 + ty * 8 + i) * N_ + b0 + tx * 8);
        mab2[i][0] = *(__half2*)&q.x; mab2[i][1] = *(__half2*)&q.y;
        mab2[i][2] = *(__half2*)&q.z; mab2[i][3] = *(__half2*)&q.w;
    }

    // Stage: each thread handles 32 c-values of one A-row or one B-row,
    // one uint4 (8 c's) at a time to keep register liveness low.
    {
        const int  sr  = tid & 127;
        const bool isB = tid >= 128;
        const __half* rowp = M + ((isB ? b0 : a0) + sr) * N_ + c0;
#pragma unroll
        for (int q = 0; q < 4; ++q) {
            uint4 v = ((const uint4*)rowp)[q];
            __half h[8];
            *(uint4*)&h[0] = v;
            const int cbase = 8 * q;
            if (!isB) {
#pragma unroll
                for (int k = 0; k < 8; ++k) {
                    __half2 p = __half2half2(__hneg(h[k]));
                    *(uint32_t*)&sA[cbase + k][2 * sr] = *(uint32_t*)&p;
                }
            } else {
#pragma unroll
                for (int k = 0; k < 8; ++k) sB[cbase + k][sr] = h[k];
            }
        }
    }
    __syncthreads();

    float facc[2] = {0.0f, 0.0f};

    // Mainloop: 4 blocks of 8 c's; REAL loop (I$-resident 8.8KB body).
#pragma unroll 1
    for (int cb = 0; cb < 32; cb += 8) {
        __half2 hacc[8];                   // per-i accs: <=32 terms each
#pragma unroll
        for (int i = 0; i < 8; ++i) hacc[i] = __float2half2_rn(0.0f);

#pragma unroll
        for (int cc = 0; cc < 8; ++cc) {
            const int c = cb + cc;
            uint4 A0 = *(const uint4*)&sA[c][ty * 16];
            uint4 A1 = *(const uint4*)&sA[c][ty * 16 + 8];
            uint4 Bv = *(const uint4*)&sB[c][tx * 8];
            __half2 a2[8], b2[4];
            a2[0] = *(__half2*)&A0.x; a2[1] = *(__half2*)&A0.y;
            a2[2] = *(__half2*)&A0.z; a2[3] = *(__half2*)&A0.w;
            a2[4] = *(__half2*)&A1.x; a2[5] = *(__half2*)&A1.y;
            a2[6] = *(__half2*)&A1.z; a2[7] = *(__half2*)&A1.w;
            b2[0] = *(__half2*)&Bv.x; b2[1] = *(__half2*)&Bv.y;
            b2[2] = *(__half2*)&Bv.z; b2[3] = *(__half2*)&Bv.w;
#pragma unroll
            for (int i = 0; i < 8; ++i) {
#pragma unroll
                for (int jp = 0; jp < 4; ++jp) {
                    // fma.rn.relu.f16x2: 2 fma-pipe instrs per half2,
                    // zero alu-pipe work.
                    hacc[i] = __hadd2(hacc[i],
                                      __hfma2_relu(a2[i], b2[jp], mab2[i][jp]));
                }
            }
        }

        // promote block accumulators to fp32 (tree into 2 accs)
        __half2 h01 = __hadd2(hacc[0], hacc[1]);
        __half2 h23 = __hadd2(hacc[2], hacc[3]);
        __half2 h45 = __hadd2(hacc[4], hacc[5]);
        __half2 h67 = __hadd2(hacc[6], hacc[7]);
        __half2 hA  = __hadd2(h01, h23);   // <=128 terms, max <128: fp16-safe
        __half2 hB  = __hadd2(h45, h67);
        facc[0] += __low2float(hA) + __high2float(hA);
        facc[1] += __low2float(hB) + __high2float(hB);
    }

    // Deterministic block reduction.
    float tsum = facc[0] + facc[1];
#pragma unroll
    for (int off = 16; off > 0; off >>= 1)
        tsum += __shfl_down_sync(0xFFFFFFFFu, tsum, off);

    __syncthreads();   // release sA before aliased reuse
    if ((tid & 31) == 0) wred[tid >> 5] = tsum;
    __syncthreads();

    // Publish partial, then elect the last-finishing CTA to do the final sum.
    if (tid == 0) {
        float s = 0.0f;
#pragma unroll
        for (int w = 0; w < 8; ++w) s += wred[w];
        const int part = ((sl * CS + cblk) * (NT * NT)) + tile;
        g_part[part] = s;
        __threadfence();
        unsigned ticket = atomicAdd(&g_ctr, 1u);
        lastf[0] = (ticket == NCTA - 1) ? 1 : 0;
    }
    __syncthreads();

    if (lastf[0]) {
        // Fixed-order deterministic final reduce over all 2048 partials.
        double s = 0.0;
#pragma unroll
        for (int k = 0; k < NCTA / 256; ++k)
            s += (double)g_part[tid + k * 256];
#pragma unroll
        for (int off = 16; off > 0; off >>= 1)
            s += __shfl_down_sync(0xFFFFFFFFu, s, off);
        if ((tid & 31) == 0) dw[tid >> 5] = s;
        __syncthreads();
        if (tid == 0) {
            double tot = 0.0;
#pragma unroll
            for (int w = 0; w < 8; ++w) tot += dw[w];
            out[0] = (float)(tot / (double)(R_ * B_));
            g_ctr = 0;   // reset for next graph replay
        }
    }
}

extern "C" void kernel_launch(void* const* d_in, const int* in_sizes, int n_in,
                              void* d_out, int out_size) {
    const float* logits = (const float*)d_in[0];
    const int*   masks  = (const int*)d_in[1];
    float*       out    = (float*)d_out;

    sigmoid_mask_kernel<<<(B_ * N_ * N_ + 255) / 256, 256>>>(logits, masks);

    dim3 g2(NT * NT, CS, S_);
    trans_relu_kernel<<<g2, 256>>>(out);
}

// round 12
// speedup vs baseline: 1.0280x; 1.0280x over previous
#include <cuda_runtime.h>
#include <cuda_fp16.h>
#include <cstdint>

// LogicalConsistencyLoss: out = sum_{s,a,b,c} relu(M_ab - M_ac*M_bc) / (R*B)
// where M = fp16(sigmoid(logits)) * mask_a * mask_b per (batch,relation) slice.
// FINAL (R10 config, best measured: 74.2us):
//  - Pass 1: sigmoid+mask -> fp16 scratch (4MB, L2-resident), R de-interleaved.
//  - Pass 2: SGEMM-style 128x128 (a,b) tiles x 32-c blocks; per-thread 8x8
//    fp16 tile; inner loop = fma.rn.relu.f16x2 + add.f16x2 (2 fma-pipe instrs
//    per half2 = algorithmic floor; relu fused, alu pipe ~idle).
//  - fp16 block accumulators promoted to fp32 every 8 c's (range-safe).
//  - Final reduction fused into last-finishing CTA (threadfence pattern),
//    fixed summation order -> deterministic.

#define B_ 2
#define N_ 512
#define R_ 4
#define S_ (B_ * R_)                   // 8 slices
#define NT (N_ / 128)                  // 4 tiles per dim
#define CS 16                          // c-split: 32 c's per CTA
#define NCTA (NT * NT * CS * S_)       // 2048 cubic CTAs / partials

__device__ __half    g_relh[S_ * N_ * N_];   // 4 MB scratch (L2-resident)
__device__ float     g_part[NCTA];
__device__ unsigned  g_ctr;                  // zero-init; reset by last CTA

// ---------------- Pass 1: sigmoid + mask -> fp16, de-interleave R ----------------
__global__ void sigmoid_mask_kernel(const float* __restrict__ logits,
                                    const int*   __restrict__ masks) {
    int idx = blockIdx.x * blockDim.x + threadIdx.x;  // over B*N*N
    if (idx >= B_ * N_ * N_) return;
    int b   = idx / (N_ * N_);
    int rem = idx - b * (N_ * N_);
    int i   = rem / N_;
    int j   = rem - i * N_;
    float mm = (masks[b * N_ + i] > 0 && masks[b * N_ + j] > 0) ? 1.0f : 0.0f;
    float4 v = ((const float4*)logits)[idx];  // 4 relations of one (b,i,j)
    float p0 = __fdividef(mm, 1.0f + __expf(-v.x));
    float p1 = __fdividef(mm, 1.0f + __expf(-v.y));
    float p2 = __fdividef(mm, 1.0f + __expf(-v.z));
    float p3 = __fdividef(mm, 1.0f + __expf(-v.w));
    g_relh[(b * R_ + 0) * N_ * N_ + rem] = __float2half(p0);
    g_relh[(b * R_ + 1) * N_ * N_ + rem] = __float2half(p1);
    g_relh[(b * R_ + 2) * N_ * N_ + rem] = __float2half(p2);
    g_relh[(b * R_ + 3) * N_ * N_ + rem] = __float2half(p3);
}

// ---------------- Pass 2: cubic relu contraction + fused final reduce ----------
// Grid: x = (a,b) tile (16), y = c-split (16), z = slice (8). 256 threads.
// Thread: 8x8 fp16 M_ab tile as 8x4 half2 regs; 8 half2 accs -> 2 f32.
__global__ void __launch_bounds__(256, 4)
trans_relu_kernel(float* __restrict__ out) {
    const int tile = blockIdx.x;      // 0..15
    const int cblk = blockIdx.y;      // 0..15
    const int sl   = blockIdx.z;      // 0..7
    const __half* __restrict__ M = g_relh + sl * N_ * N_;

    const int a0 = (tile / NT) * 128;
    const int b0 = (tile % NT) * 128;
    const int c0 = cblk * (N_ / CS);  // 32 c's per CTA

    const int tid = threadIdx.x;
    const int tx  = tid & 15;         // b sub-tile
    const int ty  = tid >> 4;         // a sub-tile

    // All 32 c's staged once.
    // sA holds NEGATED + DUPLICATED values: sA[c][2a]=sA[c][2a+1] = -M[a0+a][c]
    // so uint4 LDS yields 4 ready {-a,-a} half2 broadcast pairs.
    __shared__ __align__(16) __half sA[32][256];   // 16 KB
    __shared__ __align__(16) __half sB[32][128];   //  8 KB
    // Reduction scratch aliased into sA after the mainloop (post-sync).
    float*  wred  = reinterpret_cast<float*>(&sA[0][0]);   // 8 floats
    double* dw    = reinterpret_cast<double*>(&sA[1][0]);  // 8 doubles
    int*    lastf = reinterpret_cast<int*>(&sA[2][0]);     // amLast flag

    // 8x8 M_ab tile packed as half2 (j,j+1) pairs: 32 regs.
    __half2 mab2[8][4];
#pragma unroll
    for (int i = 0; i < 8; ++i) {
        uint4 q = *(const uint4*)(M + (a0 + ty * 8 + i) * N_ + b0 + tx * 8);
        mab2[i][0] = *(__half2*)&q.x; mab2[i][1] = *(__half2*)&q.y;
        mab2[i][2] = *(__half2*)&q.z; mab2[i][3] = *(__half2*)&q.w;
    }

    // Stage: each thread handles 32 c-values of one A-row or one B-row,
    // one uint4 (8 c's) at a time to keep register liveness low.
    {
        const int  sr  = tid & 127;
        const bool isB = tid >= 128;
        const __half* rowp = M + ((isB ? b0 : a0) + sr) * N_ + c0;
#pragma unroll
        for (int q = 0; q < 4; ++q) {
            uint4 v = ((const uint4*)rowp)[q];
            __half h[8];
            *(uint4*)&h[0] = v;
            const int cbase = 8 * q;
            if (!isB) {
#pragma unroll
                for (int k = 0; k < 8; ++k) {
                    __half2 p = __half2half2(__hneg(h[k]));
                    *(uint32_t*)&sA[cbase + k][2 * sr] = *(uint32_t*)&p;
                }
            } else {
#pragma unroll
                for (int k = 0; k < 8; ++k) sB[cbase + k][sr] = h[k];
            }
        }
    }
    __syncthreads();

    float facc[2] = {0.0f, 0.0f};

    // Mainloop: 4 blocks of 8 c's; fp32 promotion between blocks.
#pragma unroll
    for (int cb = 0; cb < 32; cb += 8) {
        __half2 hacc[8];                   // per-i accs: <=32 terms each
#pragma unroll
        for (int i = 0; i < 8; ++i) hacc[i] = __float2half2_rn(0.0f);

#pragma unroll
        for (int cc = 0; cc < 8; ++cc) {
            const int c = cb + cc;
            uint4 A0 = *(const uint4*)&sA[c][ty * 16];
            uint4 A1 = *(const uint4*)&sA[c][ty * 16 + 8];
            uint4 Bv = *(const uint4*)&sB[c][tx * 8];
            __half2 a2[8], b2[4];
            a2[0] = *(__half2*)&A0.x; a2[1] = *(__half2*)&A0.y;
            a2[2] = *(__half2*)&A0.z; a2[3] = *(__half2*)&A0.w;
            a2[4] = *(__half2*)&A1.x; a2[5] = *(__half2*)&A1.y;
            a2[6] = *(__half2*)&A1.z; a2[7] = *(__half2*)&A1.w;
            b2[0] = *(__half2*)&Bv.x; b2[1] = *(__half2*)&Bv.y;
            b2[2] = *(__half2*)&Bv.z; b2[3] = *(__half2*)&Bv.w;
#pragma unroll
            for (int i = 0; i < 8; ++i) {
#pragma unroll
                for (int jp = 0; jp < 4; ++jp) {
                    // fma.rn.relu.f16x2: 2 fma-pipe instrs per half2,
                    // zero alu-pipe work.
                    hacc[i] = __hadd2(hacc[i],
                                      __hfma2_relu(a2[i], b2[jp], mab2[i][jp]));
                }
            }
        }

        // promote block accumulators to fp32 (tree into 2 accs)
        __half2 h01 = __hadd2(hacc[0], hacc[1]);
        __half2 h23 = __hadd2(hacc[2], hacc[3]);
        __half2 h45 = __hadd2(hacc[4], hacc[5]);
        __half2 h67 = __hadd2(hacc[6], hacc[7]);
        __half2 hA  = __hadd2(h01, h23);   // <=128 terms, max <128: fp16-safe
        __half2 hB  = __hadd2(h45, h67);
        facc[0] += __low2float(hA) + __high2float(hA);
        facc[1] += __low2float(hB) + __high2float(hB);
    }

    // Deterministic block reduction.
    float tsum = facc[0] + facc[1];
#pragma unroll
    for (int off = 16; off > 0; off >>= 1)
        tsum += __shfl_down_sync(0xFFFFFFFFu, tsum, off);

    __syncthreads();   // release sA before aliased reuse
    if ((tid & 31) == 0) wred[tid >> 5] = tsum;
    __syncthreads();

    // Publish partial, then elect the last-finishing CTA to do the final sum.
    if (tid == 0) {
        float s = 0.0f;
#pragma unroll
        for (int w = 0; w < 8; ++w) s += wred[w];
        const int part = ((sl * CS + cblk) * (NT * NT)) + tile;
        g_part[part] = s;
        __threadfence();
        unsigned ticket = atomicAdd(&g_ctr, 1u);
        lastf[0] = (ticket == NCTA - 1) ? 1 : 0;
    }
    __syncthreads();

    if (lastf[0]) {
        // Fixed-order deterministic final reduce over all 2048 partials.
        double s = 0.0;
#pragma unroll
        for (int k = 0; k < NCTA / 256; ++k)
            s += (double)g_part[tid + k * 256];
#pragma unroll
        for (int off = 16; off > 0; off >>= 1)
            s += __shfl_down_sync(0xFFFFFFFFu, s, off);
        if ((tid & 31) == 0) dw[tid >> 5] = s;
        __syncthreads();
        if (tid == 0) {
            double tot = 0.0;
#pragma unroll
            for (int w = 0; w < 8; ++w) tot += dw[w];
            out[0] = (float)(tot / (double)(R_ * B_));
            g_ctr = 0;   // reset for next graph replay
        }
    }
}

extern "C" void kernel_launch(void* const* d_in, const int* in_sizes, int n_in,
                              void* d_out, int out_size) {
    const float* logits = (const float*)d_in[0];
    const int*   masks  = (const int*)d_in[1];
    float*       out    = (float*)d_out;

    sigmoid_mask_kernel<<<(B_ * N_ * N_ + 255) / 256, 256>>>(logits, masks);

    dim3 g2(NT * NT, CS, S_);
    trans_relu_kernel<<<g2, 256>>>(out);
}